// round 2
// baseline (speedup 1.0000x reference)
#include <cuda_runtime.h>
#include <cuda_bf16.h>
#include <cstdint>

#define DN 256          // number of nodes (D)
#define HN 64           // hidden width (H)
#define BN 8192         // batch
#define ROWS 64         // rows per block
#define THREADS 256
#define NBLOCKS (BN / ROWS)   // 128

// Masked, transposed weights: Wt[i][j][k] = W1[i,k,j] * sigmoid(adj_logits[j,i]) * (j != i)
__device__ float g_Wt[DN * DN * HN];   // 16.8 MB scratch (L2-resident)

typedef unsigned long long u64;

// ---------------- packed f32x2 helpers (sm_103a) ----------------
__device__ __forceinline__ u64 pack2(float lo, float hi) {
    u64 r;
    asm("mov.b64 %0, {%1, %2};" : "=l"(r) : "f"(lo), "f"(hi));
    return r;
}
__device__ __forceinline__ void unpack2(u64 v, float& lo, float& hi) {
    asm("mov.b64 {%0, %1}, %2;" : "=f"(lo), "=f"(hi) : "l"(v));
}
__device__ __forceinline__ u64 fma2(u64 a, u64 b, u64 c) {
    u64 d;
    asm("fma.rn.f32x2 %0, %1, %2, %3;" : "=l"(d) : "l"(a), "l"(b), "l"(c));
    return d;
}

__device__ __forceinline__ void cp_async16(void* smem_dst, const void* gsrc) {
    uint32_t s = (uint32_t)__cvta_generic_to_shared(smem_dst);
    asm volatile("cp.async.cg.shared.global [%0], [%1], 16;" :: "r"(s), "l"(gsrc));
}
__device__ __forceinline__ void cp_commit() {
    asm volatile("cp.async.commit_group;");
}
__device__ __forceinline__ void cp_wait_all() {
    asm volatile("cp.async.wait_group 0;" ::: "memory");
}

// ---------------- precompute: fold adjacency sigmoid into transposed weights ----------------
__global__ void precompute_kernel(const float* __restrict__ W1,
                                  const float* __restrict__ adj_logits) {
    int i = blockIdx.x;
    __shared__ float tile[64][65];
    __shared__ float asig[64];
    const float* W1i = W1 + (size_t)i * HN * DN;   // [H][D], j fastest
    float* Wti = g_Wt + (size_t)i * DN * HN;       // [D][H], k fastest

    for (int j0 = 0; j0 < DN; j0 += 64) {
        for (int idx = threadIdx.x; idx < 64 * 64; idx += blockDim.x) {
            int k = idx >> 6, jj = idx & 63;
            tile[k][jj] = W1i[k * DN + j0 + jj];          // coalesced read
        }
        if (threadIdx.x < 64) {
            int j = j0 + threadIdx.x;
            float l = adj_logits[j * DN + i];
            float s = 1.0f / (1.0f + __expf(-l));
            asig[threadIdx.x] = (j == i) ? 0.0f : s;
        }
        __syncthreads();
        for (int idx = threadIdx.x; idx < 64 * 64; idx += blockDim.x) {
            int jj = idx >> 6, k = idx & 63;
            Wti[(j0 + jj) * HN + k] = tile[k][jj] * asig[jj];  // coalesced write
        }
        __syncthreads();
    }
}

// ---------------- main sequential-per-row kernel ----------------
// Thread map: 256 threads cover the 64x64 (rows x hidden-k) output tile.
//   tk  = lane & 7   -> k-chunk (8 consecutive k)
//   trl = lane >> 3  -> row-chunk within warp
//   tr  = wid*4+trl  -> row pair id (2 rows per thread)
// k-reduction after the GEMM is an 8-lane shuffle group (width=8).
//
// smem: z_s[DN][ROWS] (64 KB) | W buffers 2 x [DN][HN] (2 x 64 KB) = 192 KB
extern __shared__ float smem_dyn[];

__global__ void __launch_bounds__(THREADS, 1)
scm_kernel(const float* __restrict__ noise,
           const float* __restrict__ b1,
           const float* __restrict__ W2,
           const float* __restrict__ b2,
           const float* __restrict__ log_sigma,
           float* __restrict__ out) {
    float* z_s = smem_dyn;                   // [DN][ROWS], j-major
    float* W_b = smem_dyn + DN * ROWS;       // two buffers of [DN][HN]

    const int tid  = threadIdx.x;
    const int lane = tid & 31;
    const int wid  = tid >> 5;
    const int tk   = lane & 7;
    const int trl  = lane >> 3;
    const int tr   = wid * 4 + trl;          // 0..31
    const int r0   = 2 * tr;                 // first of this thread's 2 rows
    const int kb   = 8 * tk;                 // first of this thread's 8 k
    const int row0 = blockIdx.x * ROWS;

    // zero z (columns >= i read as zero in the rounded-up K loop)
    for (int idx = tid; idx < DN * ROWS; idx += THREADS) z_s[idx] = 0.0f;
    __syncthreads();

    for (int i = 0; i < DN; ++i) {
        cp_wait_all();
        __syncthreads();   // W[i] ready in buffer (i&1)

        // prefetch W for node i+1 into the other buffer (overlaps compute)
        if (i + 1 < DN) {
            int jn = (i + 4) & ~3; if (jn > DN) jn = DN;
            const float4* src = (const float4*)(g_Wt + (size_t)(i + 1) * DN * HN);
            float4* dst = (float4*)(W_b + ((i + 1) & 1) * DN * HN);
            for (int idx = tid; idx < jn * (HN / 4); idx += THREADS)
                cp_async16(dst + idx, src + idx);
        }
        cp_commit();

        int jmax = (i + 3) & ~3; if (jmax > DN) jmax = DN;
        const float* W_s = W_b + (i & 1) * DN * HN;

        // acc[r][p]: rows (r0+r), k-pair p -> k = kb+2p, kb+2p+1 (packed f32x2)
        u64 acc[2][4];
        #pragma unroll
        for (int p = 0; p < 4; ++p) { acc[0][p] = 0ull; acc[1][p] = 0ull; }

        const float* zcol = z_s + r0;
        const u64* wrow = (const u64*)(W_s + kb);

        #pragma unroll 4
        for (int j = 0; j < jmax; ++j) {
            // this thread's 2 z rows (vector LDS.64, conflict-free)
            u64 zv = *(const u64*)(zcol + j * ROWS);
            float zlo, zhi;
            unpack2(zv, zlo, zhi);
            u64 zd0 = pack2(zlo, zlo);
            u64 zd1 = pack2(zhi, zhi);
            // 8 weights as 4 naturally-packed pairs (2x LDS.128, no pack MOVs)
            const u64* wj = wrow + j * (HN / 2);
            u64 w0 = wj[0], w1 = wj[1], w2p = wj[2], w3 = wj[3];
            acc[0][0] = fma2(w0,  zd0, acc[0][0]);
            acc[0][1] = fma2(w1,  zd0, acc[0][1]);
            acc[0][2] = fma2(w2p, zd0, acc[0][2]);
            acc[0][3] = fma2(w3,  zd0, acc[0][3]);
            acc[1][0] = fma2(w0,  zd1, acc[1][0]);
            acc[1][1] = fma2(w1,  zd1, acc[1][1]);
            acc[1][2] = fma2(w2p, zd1, acc[1][2]);
            acc[1][3] = fma2(w3,  zd1, acc[1][3]);
        }

        // per-node params for this thread's 8 k values
        float4 b1a = __ldg((const float4*)(b1 + i * HN + kb));
        float4 b1b = __ldg((const float4*)(b1 + i * HN + kb + 4));
        float4 w2a = __ldg((const float4*)(W2 + i * HN + kb));
        float4 w2b = __ldg((const float4*)(W2 + i * HN + kb + 4));
        float b1v[8] = {b1a.x, b1a.y, b1a.z, b1a.w, b1b.x, b1b.y, b1b.z, b1b.w};
        float w2v[8] = {w2a.x, w2a.y, w2a.z, w2a.w, w2b.x, w2b.y, w2b.z, w2b.w};

        // epilogue: h = silu(acc + b1), s = h . w2 over this thread's 8 k,
        // then reduce across the 8-lane tk group.
        float red[2];
        #pragma unroll
        for (int r = 0; r < 2; ++r) {
            float s = 0.0f;
            #pragma unroll
            for (int p = 0; p < 4; ++p) {
                float alo, ahi;
                unpack2(acc[r][p], alo, ahi);
                float x0 = alo + b1v[2 * p];
                float x1 = ahi + b1v[2 * p + 1];
                s += __fdividef(x0, 1.0f + __expf(-x0)) * w2v[2 * p];
                s += __fdividef(x1, 1.0f + __expf(-x1)) * w2v[2 * p + 1];
            }
            s += __shfl_xor_sync(0xffffffffu, s, 1, 8);
            s += __shfl_xor_sync(0xffffffffu, s, 2, 8);
            s += __shfl_xor_sync(0xffffffffu, s, 4, 8);
            red[r] = s;
        }

        if (tk == 0) {
            float b2i = __ldg(b2 + i);
            float sig = __expf(__ldg(log_sigma + i));
            #pragma unroll
            for (int r = 0; r < 2; ++r) {
                float val = red[r] + b2i +
                            sig * __ldg(noise + (size_t)(row0 + r0 + r) * DN + i);
                z_s[i * ROWS + r0 + r] = val;
            }
        }
        __syncthreads();   // z column i visible before node i+1 reads it
    }

    // write out z: global-coalesced
    for (int idx = tid; idx < ROWS * DN; idx += THREADS) {
        int r = idx >> 8;        // 0..63
        int j = idx & 255;       // 0..255
        out[(size_t)(row0 + r) * DN + j] = z_s[j * ROWS + r];
    }
}

extern "C" void kernel_launch(void* const* d_in, const int* in_sizes, int n_in,
                              void* d_out, int out_size) {
    const float* noise      = (const float*)d_in[0];
    const float* adj_logits = (const float*)d_in[1];
    const float* W1         = (const float*)d_in[2];
    const float* b1         = (const float*)d_in[3];
    const float* W2         = (const float*)d_in[4];
    const float* b2         = (const float*)d_in[5];
    const float* log_sigma  = (const float*)d_in[6];
    float* out = (float*)d_out;

    precompute_kernel<<<DN, 256>>>(W1, adj_logits);

    size_t smem_bytes = (size_t)(DN * ROWS + 2 * DN * HN) * sizeof(float);  // 192 KB
    cudaFuncSetAttribute(scm_kernel, cudaFuncAttributeMaxDynamicSharedMemorySize,
                         (int)smem_bytes);
    scm_kernel<<<NBLOCKS, THREADS, smem_bytes>>>(noise, b1, W2, b2, log_sigma, out);
}